// round 2
// baseline (speedup 1.0000x reference)
#include <cuda_runtime.h>
#include <cuda_bf16.h>

// Problem constants
#define MAX_N     512
#define N_CLASSES 64
#define MESH_DIM  128
#define NUM_CLUT  5
#define BANK_SIZE 4096
#define BATCH     4
#define FEAT_ROWS (MAX_N + NUM_CLUT)          // 517
#define CJ        (N_CLASSES * MAX_N)          // 32768
#define NCLUT_TOT (NUM_CLUT * BANK_SIZE)       // 20480
#define NTOT      (CJ + NCLUT_TOT)             // 53248
#define M_TOT     (BATCH * MAX_N)              // 2048

// Output offsets (element counts)
#define OUT_SIM_OFF   0ULL
#define OUT_SIM_SZ    ((unsigned long long)BATCH * MAX_N * NTOT)              // 109,051,904
#define OUT_NSIM_OFF  (OUT_SIM_OFF + OUT_SIM_SZ)
#define OUT_NSIM_SZ   ((unsigned long long)BATCH * NUM_CLUT * CJ)             // 655,360
#define OUT_MEM_OFF   (OUT_NSIM_OFF + OUT_NSIM_SZ)
#define OUT_MEM_SZ    ((unsigned long long)N_CLASSES * MESH_DIM * MAX_N)      // 4,194,304
#define OUT_CB_OFF    (OUT_MEM_OFF + OUT_MEM_SZ)

// ---------------------------------------------------------------------------
// Packed fp32x2 FMA helpers (FFMA2 — 2x fp32 FMA throughput on sm_103a)
// ---------------------------------------------------------------------------
__device__ __forceinline__ void ffma2(unsigned long long& d,
                                      unsigned long long a,
                                      unsigned long long b) {
    asm("fma.rn.f32x2 %0, %1, %2, %0;" : "+l"(d) : "l"(a), "l"(b));
}
__device__ __forceinline__ void unpack2(float& x, float& y, unsigned long long d) {
    asm("mov.b64 {%0, %1}, %2;" : "=f"(x), "=f"(y) : "l"(d));
}

// ---------------------------------------------------------------------------
// Kernel 1: similarity GEMM.
//   A: vertices  (M_TOT x 128), row m = b*512+i -> features row (b*517+i)
//   W: columns 0..32767   -> memory[c][k][j]   (c=n>>9, j=n&511, ld=512)
//      columns 32768..    -> clutter_bank[k][n-32768]  (ld=20480)
//   out[m][n] = sum_k A[m][k]*W[k][n]
// Tiling: BM=BN=128, BK=8, 256 threads, per-thread 8(m, paired)x8(n, stride16)
// ---------------------------------------------------------------------------
#define BM 128
#define BN 128
#define BK 8

__global__ __launch_bounds__(256)
void sim_gemm_kernel(const float* __restrict__ features,
                     const float* __restrict__ memory,
                     const float* __restrict__ clutter,
                     float* __restrict__ out) {
    __shared__ float As[BK][BM];        // A transposed:  As[k][m]
    __shared__ float Ws[BK][2 * BN];    // W duplicated:  Ws[k][2n]=Ws[k][2n+1]=w

    const int t  = threadIdx.x;
    const int tx = t & 15;
    const int ty = t >> 4;

    const int n0 = blockIdx.x * BN;
    const int m0 = blockIdx.y * BM;

    // A base: rows of tile all in same image b (512 % 128 == 0)
    const int b  = m0 >> 9;
    const int i0 = m0 & 511;
    const float* Abase = features + ((size_t)(b * FEAT_ROWS + i0)) * MESH_DIM;

    // W base & leading dim
    const float* Wbase;
    int ldw;
    if (n0 < CJ) {
        const int c  = n0 >> 9;
        const int j0 = n0 & 511;
        Wbase = memory + (size_t)c * (MESH_DIM * MAX_N) + j0;
        ldw   = MAX_N;          // 512
    } else {
        Wbase = clutter + (n0 - CJ);
        ldw   = NCLUT_TOT;      // 20480
    }

    unsigned long long acc[8][4];
#pragma unroll
    for (int q = 0; q < 8; q++)
#pragma unroll
        for (int p = 0; p < 4; p++) acc[q][p] = 0ULL;

    // loader index precompute
    const int arow  = t >> 1;          // 0..127
    const int ahalf = t & 1;           // which float4 of the 8-wide k chunk
    const int wrow  = t >> 5;          // 0..7
    const int wcol  = (t & 31) * 4;    // 0..124

    for (int k0 = 0; k0 < MESH_DIM; k0 += BK) {
        // --- load A tile (transposed into smem) ---
        float4 av = *reinterpret_cast<const float4*>(Abase + (size_t)arow * MESH_DIM + k0 + ahalf * 4);
        As[ahalf * 4 + 0][arow] = av.x;
        As[ahalf * 4 + 1][arow] = av.y;
        As[ahalf * 4 + 2][arow] = av.z;
        As[ahalf * 4 + 3][arow] = av.w;

        // --- load W tile (duplicated pairs for f32x2 broadcast) ---
        float4 wv = *reinterpret_cast<const float4*>(Wbase + (size_t)(k0 + wrow) * ldw + wcol);
        Ws[wrow][2 * (wcol + 0)] = wv.x; Ws[wrow][2 * (wcol + 0) + 1] = wv.x;
        Ws[wrow][2 * (wcol + 1)] = wv.y; Ws[wrow][2 * (wcol + 1) + 1] = wv.y;
        Ws[wrow][2 * (wcol + 2)] = wv.z; Ws[wrow][2 * (wcol + 2) + 1] = wv.z;
        Ws[wrow][2 * (wcol + 3)] = wv.w; Ws[wrow][2 * (wcol + 3) + 1] = wv.w;

        __syncthreads();

#pragma unroll
        for (int k = 0; k < BK; k++) {
            unsigned long long ap[4];
#pragma unroll
            for (int p = 0; p < 4; p++)
                ap[p] = *reinterpret_cast<const unsigned long long*>(&As[k][ty * 8 + 2 * p]);
#pragma unroll
            for (int q = 0; q < 8; q++) {
                unsigned long long wq =
                    *reinterpret_cast<const unsigned long long*>(&Ws[k][2 * (tx + 16 * q)]);
#pragma unroll
                for (int p = 0; p < 4; p++) ffma2(acc[q][p], ap[p], wq);
            }
        }
        __syncthreads();
    }

    // --- epilogue: per warp, 16 consecutive 4B per half-warp (64B segments) ---
#pragma unroll
    for (int q = 0; q < 8; q++) {
        const int n = n0 + tx + 16 * q;
        float* col = out + n;
#pragma unroll
        for (int p = 0; p < 4; p++) {
            const int m = m0 + ty * 8 + 2 * p;
            float x, y;
            unpack2(x, y, acc[q][p]);
            col[(size_t)m * NTOT]       = x;
            col[(size_t)(m + 1) * NTOT] = y;
        }
    }
}

// ---------------------------------------------------------------------------
// Kernel 2: noise similarity.  out[r][c*512+j] = sum_v noise[r][v]*memory[c][v][j]
// r = b*5+k (20 rows).  One block per (jtile, c); memory read exactly once.
// ---------------------------------------------------------------------------
__global__ __launch_bounds__(256)
void noise_sim_kernel(const float* __restrict__ features,
                      const float* __restrict__ memory,
                      float* __restrict__ out) {
    __shared__ float ns[BATCH * NUM_CLUT][MESH_DIM];   // 20 x 128

    const int c = blockIdx.y;
    const int j = blockIdx.x * 256 + threadIdx.x;

    for (int idx = threadIdx.x; idx < BATCH * NUM_CLUT * MESH_DIM; idx += 256) {
        const int r = idx >> 7;          // 0..19
        const int v = idx & 127;
        const int bb = r / NUM_CLUT;
        const int kk = r % NUM_CLUT;
        ns[r][v] = features[(size_t)(bb * FEAT_ROWS + MAX_N + kk) * MESH_DIM + v];
    }
    __syncthreads();

    float acc[BATCH * NUM_CLUT];
#pragma unroll
    for (int r = 0; r < BATCH * NUM_CLUT; r++) acc[r] = 0.0f;

    const float* mp = memory + (size_t)c * (MESH_DIM * MAX_N) + j;
#pragma unroll 4
    for (int v = 0; v < MESH_DIM; v++) {
        const float mv = mp[(size_t)v * MAX_N];
#pragma unroll
        for (int r = 0; r < BATCH * NUM_CLUT; r++) acc[r] += ns[r][v] * mv;
    }

#pragma unroll
    for (int r = 0; r < BATCH * NUM_CLUT; r++)
        out[(size_t)r * CJ + c * MAX_N + j] = acc[r];
}

// ---------------------------------------------------------------------------
// Kernel 3: memory update.
// new_memory[c][v][j] = l2n_over_v( cnt==0 ? mem : 0.9*mem + 0.1*mean_b(vert*vis) )
// Block: (c, 32-wide j tile); 256 threads = 8 v-groups x 32 j.
// visible arrives as int32 (harness coerces bool -> int32).
// ---------------------------------------------------------------------------
__global__ __launch_bounds__(256)
void mem_update_kernel(const float* __restrict__ features,
                       const int* __restrict__ visible,
                       const int* __restrict__ label,
                       const float* __restrict__ memory,
                       float* __restrict__ out) {
    __shared__ float tile[MESH_DIM][32];
    __shared__ float ssqs[8][32];

    const int c  = blockIdx.y;
    const int j0 = blockIdx.x * 32;
    const int t  = threadIdx.x;
    const int jx = t & 31;
    const int vy = t >> 5;                 // 0..7
    const int j  = j0 + jx;

    int lbl[BATCH];
#pragma unroll
    for (int bb = 0; bb < BATCH; bb++) lbl[bb] = label[bb];

    int cnt = 0;
#pragma unroll
    for (int bb = 0; bb < BATCH; bb++) cnt += (lbl[bb] == c) ? 1 : 0;

    float w[BATCH];
    const float inv = (cnt > 0) ? (1.0f / (float)cnt) : 0.0f;
#pragma unroll
    for (int bb = 0; bb < BATCH; bb++)
        w[bb] = (lbl[bb] == c && visible[bb * MAX_N + j] != 0) ? inv : 0.0f;

    float ssq = 0.0f;
#pragma unroll
    for (int vv = 0; vv < 16; vv++) {
        const int v = vy * 16 + vv;
        const float m = memory[(size_t)c * (MESH_DIM * MAX_N) + (size_t)v * MAX_N + j];
        float val;
        if (cnt == 0) {
            val = m;
        } else {
            float s = 0.0f;
#pragma unroll
            for (int bb = 0; bb < BATCH; bb++)
                s += w[bb] * features[(size_t)(bb * FEAT_ROWS + j) * MESH_DIM + v];
            val = 0.9f * m + 0.1f * s;
        }
        tile[v][jx] = val;
        ssq += val * val;
    }
    ssqs[vy][jx] = ssq;
    __syncthreads();

    float tot = 0.0f;
#pragma unroll
    for (int y = 0; y < 8; y++) tot += ssqs[y][jx];
    const float rn = 1.0f / fmaxf(sqrtf(tot), 1e-12f);

#pragma unroll
    for (int vv = 0; vv < 16; vv++) {
        const int v = vy * 16 + vv;
        out[(size_t)c * (MESH_DIM * MAX_N) + (size_t)v * MAX_N + j] = tile[v][jx] * rn;
    }
}

// ---------------------------------------------------------------------------
// Kernel 4: clutter bank update (LRU insert + column l2 renormalize).
// ---------------------------------------------------------------------------
__global__ __launch_bounds__(128)
void clutter_kernel(const float* __restrict__ clutter,
                    const float* __restrict__ features,
                    const int* __restrict__ lru,
                    float* __restrict__ out) {
    const int n = blockIdx.x * 128 + threadIdx.x;     // 0..20479
    const int new_lru = (lru[0] + 1) % (BANK_SIZE / BATCH);
    const int start = new_lru * (NUM_CLUT * BATCH);

    const bool upd = (n >= start) && (n < start + NUM_CLUT * BATCH);
    const int m  = n - start;
    const int bb = upd ? (m / NUM_CLUT) : 0;
    const int kk = upd ? (m % NUM_CLUT) : 0;
    const float* nsrc = features + (size_t)(bb * FEAT_ROWS + MAX_N + kk) * MESH_DIM;

    float ssq = 0.0f;
#pragma unroll 4
    for (int v = 0; v < MESH_DIM; v++) {
        const float val = upd ? nsrc[v] : clutter[(size_t)v * NCLUT_TOT + n];
        ssq += val * val;
    }
    const float rn = 1.0f / fmaxf(sqrtf(ssq), 1e-12f);

#pragma unroll 4
    for (int v = 0; v < MESH_DIM; v++) {
        const float val = upd ? nsrc[v] : clutter[(size_t)v * NCLUT_TOT + n];
        out[(size_t)v * NCLUT_TOT + n] = val * rn;
    }
}

// ---------------------------------------------------------------------------
// Launcher
// ---------------------------------------------------------------------------
extern "C" void kernel_launch(void* const* d_in, const int* in_sizes, int n_in,
                              void* d_out, int out_size) {
    const float* features = (const float*)d_in[0];
    const int*   visible  = (const int*)d_in[1];
    const int*   label    = (const int*)d_in[2];
    const float* memory   = (const float*)d_in[3];
    const float* clutter  = (const float*)d_in[4];
    const int*   lru      = (const int*)d_in[5];

    float* out = (float*)d_out;
    float* out_sim  = out + OUT_SIM_OFF;
    float* out_nsim = out + OUT_NSIM_OFF;
    float* out_mem  = out + OUT_MEM_OFF;
    float* out_cb   = out + OUT_CB_OFF;

    // Small kernels first (they're independent; GEMM dominates anyway)
    noise_sim_kernel<<<dim3(2, N_CLASSES), 256>>>(features, memory, out_nsim);
    mem_update_kernel<<<dim3(MAX_N / 32, N_CLASSES), 256>>>(features, visible, label,
                                                            memory, out_mem);
    clutter_kernel<<<NCLUT_TOT / 128, 128>>>(clutter, features, lru, out_cb);

    sim_gemm_kernel<<<dim3(NTOT / BN, M_TOT / BM), 256>>>(features, memory, clutter,
                                                          out_sim);
}

// round 4
// speedup vs baseline: 2.2882x; 2.2882x over previous
#include <cuda_runtime.h>
#include <cuda_bf16.h>
#include <cstdint>

// Problem constants
#define MAX_N     512
#define N_CLASSES 64
#define MESH_DIM  128
#define NUM_CLUT  5
#define BANK_SIZE 4096
#define BATCH     4
#define FEAT_ROWS (MAX_N + NUM_CLUT)          // 517
#define CJ        (N_CLASSES * MAX_N)          // 32768
#define NCLUT_TOT (NUM_CLUT * BANK_SIZE)       // 20480
#define NTOT      (CJ + NCLUT_TOT)             // 53248
#define M_TOT     (BATCH * MAX_N)              // 2048

// Output offsets (element counts)
#define OUT_SIM_OFF   0ULL
#define OUT_SIM_SZ    ((unsigned long long)BATCH * MAX_N * NTOT)
#define OUT_NSIM_OFF  (OUT_SIM_OFF + OUT_SIM_SZ)
#define OUT_NSIM_SZ   ((unsigned long long)BATCH * NUM_CLUT * CJ)
#define OUT_MEM_OFF   (OUT_NSIM_OFF + OUT_NSIM_SZ)
#define OUT_MEM_SZ    ((unsigned long long)N_CLASSES * MESH_DIM * MAX_N)
#define OUT_CB_OFF    (OUT_MEM_OFF + OUT_MEM_SZ)

// ---------------------------------------------------------------------------
// tf32 scratch (device globals — allocation-free rule).
// Layout: row-major [m][k] / [n][k], k permuted within 8-blocks so that
// logical cols (t, t+4) sit at positions (2t, 2t+1)  -> fragment LDS.64.
// ---------------------------------------------------------------------------
__device__ __align__(16) float g_A [(size_t)M_TOT * MESH_DIM];   // 1 MB
__device__ __align__(16) float g_Wt[(size_t)NTOT  * MESH_DIM];   // 27.25 MB

__device__ __host__ __forceinline__ int kpos(int k) {
    return (k & ~7) | (((k & 3) << 1) | ((k >> 2) & 1));
}

__device__ __forceinline__ float to_tf32(float x) {
    uint32_t u;
    asm("cvt.rna.tf32.f32 %0, %1;" : "=r"(u) : "f"(x));
    return __uint_as_float(u);
}

__device__ __forceinline__ uint32_t smem_u32(const void* p) {
    uint32_t a;
    asm("{ .reg .u64 t; cvta.to.shared.u64 t, %1; cvt.u32.u64 %0, t; }" : "=r"(a) : "l"(p));
    return a;
}

#define CP_ASYNC16(saddr, gptr) \
    asm volatile("cp.async.cg.shared.global [%0], [%1], 16;" :: "r"(saddr), "l"(gptr))
#define CP_COMMIT() asm volatile("cp.async.commit_group;")
#define CP_WAIT0()  asm volatile("cp.async.wait_group 0;")

// m16n8k8 tf32 MMA (sm_80 baseline — works at compute_103)
__device__ __forceinline__ void mma_tf32(float& c0, float& c1, float& c2, float& c3,
                                         uint32_t a0, uint32_t a1, uint32_t a2, uint32_t a3,
                                         uint32_t b0, uint32_t b1) {
    asm volatile(
        "mma.sync.aligned.m16n8k8.row.col.f32.tf32.tf32.f32 "
        "{%0,%1,%2,%3}, {%4,%5,%6,%7}, {%8,%9}, {%0,%1,%2,%3};"
        : "+f"(c0), "+f"(c1), "+f"(c2), "+f"(c3)
        : "r"(a0), "r"(a1), "r"(a2), "r"(a3), "r"(b0), "r"(b1));
}

// ---------------------------------------------------------------------------
// Conversion kernels: fp32 -> tf32-rounded fp32, k-permuted layout
// ---------------------------------------------------------------------------
__global__ __launch_bounds__(256)
void convert_a_kernel(const float* __restrict__ features) {
    for (int idx = blockIdx.x * 256 + threadIdx.x; idx < M_TOT * MESH_DIM;
         idx += gridDim.x * 256) {
        const int m = idx >> 7;
        const int k = idx & 127;
        const int b = m >> 9;
        const int i = m & 511;
        const float x = features[(size_t)(b * FEAT_ROWS + i) * MESH_DIM + k];
        g_A[((size_t)m << 7) | kpos(k)] = to_tf32(x);
    }
}

// Transpose W into [n][k] tf32 via smem tile (128 k x 32 n)
__global__ __launch_bounds__(256)
void convert_w_kernel(const float* __restrict__ memory,
                      const float* __restrict__ clutter) {
    __shared__ float tile[MESH_DIM][33];

    const int blk = blockIdx.x;
    const float* src;
    int ld, nbase;
    if (blk < 1024) {       // memory part: 64 classes x 16 j-tiles
        const int c  = blk >> 4;
        const int j0 = (blk & 15) * 32;
        src   = memory + (size_t)c * (MESH_DIM * MAX_N) + j0;
        ld    = MAX_N;
        nbase = c * MAX_N + j0;
    } else {                // clutter part: 640 n-tiles
        const int n0 = (blk - 1024) * 32;
        src   = clutter + n0;
        ld    = NCLUT_TOT;
        nbase = CJ + n0;
    }

    for (int e = threadIdx.x; e < MESH_DIM * 32; e += 256) {
        const int k  = e >> 5;
        const int jx = e & 31;
        tile[k][jx] = src[(size_t)k * ld + jx];
    }
    __syncthreads();

    const int jx = threadIdx.x >> 3;         // 0..31
    const int kc = (threadIdx.x & 7) * 16;   // 0..112
    float* dst = &g_Wt[(size_t)(nbase + jx) * MESH_DIM];
#pragma unroll
    for (int i = 0; i < 16; i++) {
        const int k = kc + i;
        dst[kpos(k)] = to_tf32(tile[k][jx]);
    }
}

// ---------------------------------------------------------------------------
// tf32 mma.sync GEMM.
//   out[m][n] = A[m][:128] . W[:][n]
// Grid: 416 CTAs x 256 threads. W tile (128n x 128k) resident in smem;
// A 128x128 m-tiles double-buffered via cp.async. 8 warps = 2(m) x 4(n),
// warp tile 64m x 32n. smem ld = 136 floats (conflict-free LDS.64 frags).
// ---------------------------------------------------------------------------
#define LDK 136
#define TILE_FLOATS (128 * LDK)

__global__ __launch_bounds__(256)
void sim_gemm_tf32_kernel(float* __restrict__ out) {
    extern __shared__ float smem[];
    float* Ws  = smem;                     // [128][136]
    float* As0 = smem + TILE_FLOATS;
    float* As1 = As0 + TILE_FLOATS;

    const int tid  = threadIdx.x;
    const int wid  = tid >> 5;
    const int lane = tid & 31;
    const int g    = lane >> 2;            // 0..7
    const int tg   = lane & 3;             // 0..3
    const int wm   = (wid >> 2) * 64;      // 0 / 64
    const int wn   = (wid & 3) * 32;       // 0..96
    const int n0   = blockIdx.x * 128;

    // ---- initial loads: W tile + A tile 0 (cp.async) ----
    {
        const float* wsrc = g_Wt + (size_t)n0 * MESH_DIM;
        const uint32_t wbase = smem_u32(Ws);
        const float* asrc = g_A;
        const uint32_t abase = smem_u32(As0);
        for (int c = tid; c < 4096; c += 256) {
            const int row = c >> 5, cid = c & 31;
            CP_ASYNC16(wbase + (uint32_t)(row * LDK + cid * 4) * 4,
                       wsrc + (size_t)row * MESH_DIM + cid * 4);
            CP_ASYNC16(abase + (uint32_t)(row * LDK + cid * 4) * 4,
                       asrc + (size_t)row * MESH_DIM + cid * 4);
        }
        CP_COMMIT();
        CP_WAIT0();
    }
    __syncthreads();

    float* bufs[2] = { As0, As1 };

    for (int mt = 0; mt < 16; mt++) {
        const float* cur = bufs[mt & 1];

        // prefetch next A tile into the other buffer
        if (mt < 15) {
            const float* asrc = g_A + ((size_t)(mt + 1) * 128) * MESH_DIM;
            const uint32_t abase = smem_u32(bufs[(mt + 1) & 1]);
            for (int c = tid; c < 4096; c += 256) {
                const int row = c >> 5, cid = c & 31;
                CP_ASYNC16(abase + (uint32_t)(row * LDK + cid * 4) * 4,
                           asrc + (size_t)row * MESH_DIM + cid * 4);
            }
            CP_COMMIT();
        }

        float acc[4][4][4];
#pragma unroll
        for (int mi = 0; mi < 4; mi++)
#pragma unroll
            for (int ni = 0; ni < 4; ni++)
#pragma unroll
                for (int r = 0; r < 4; r++) acc[mi][ni][r] = 0.0f;

#pragma unroll
        for (int ks = 0; ks < 16; ks++) {
            const int colb = ks * 8 + 2 * tg;

            uint32_t a0[4], a1[4], a2[4], a3[4];
#pragma unroll
            for (int mi = 0; mi < 4; mi++) {
                const float* p = &cur[(wm + mi * 16 + g) * LDK + colb];
                const float2 lo = *reinterpret_cast<const float2*>(p);
                const float2 hi = *reinterpret_cast<const float2*>(p + 8 * LDK);
                a0[mi] = __float_as_uint(lo.x);   // (g,     tg)
                a2[mi] = __float_as_uint(lo.y);   // (g,     tg+4)
                a1[mi] = __float_as_uint(hi.x);   // (g+8,   tg)
                a3[mi] = __float_as_uint(hi.y);   // (g+8,   tg+4)
            }
            uint32_t b0[4], b1[4];
#pragma unroll
            for (int ni = 0; ni < 4; ni++) {
                const float2 bv = *reinterpret_cast<const float2*>(
                    &Ws[(wn + ni * 8 + g) * LDK + colb]);
                b0[ni] = __float_as_uint(bv.x);   // (k=tg,   n=g)
                b1[ni] = __float_as_uint(bv.y);   // (k=tg+4, n=g)
            }
#pragma unroll
            for (int mi = 0; mi < 4; mi++)
#pragma unroll
                for (int ni = 0; ni < 4; ni++)
                    mma_tf32(acc[mi][ni][0], acc[mi][ni][1],
                             acc[mi][ni][2], acc[mi][ni][3],
                             a0[mi], a1[mi], a2[mi], a3[mi],
                             b0[ni], b1[ni]);
        }

        // ---- store D tile ----
#pragma unroll
        for (int mi = 0; mi < 4; mi++) {
            const size_t m = (size_t)(mt * 128 + wm + mi * 16 + g);
#pragma unroll
            for (int ni = 0; ni < 4; ni++) {
                float* o = out + m * NTOT + (n0 + wn + ni * 8 + 2 * tg);
                float2 v0; v0.x = acc[mi][ni][0]; v0.y = acc[mi][ni][1];
                float2 v1; v1.x = acc[mi][ni][2]; v1.y = acc[mi][ni][3];
                *reinterpret_cast<float2*>(o)              = v0;   // row m
                *reinterpret_cast<float2*>(o + 8 * NTOT)   = v1;   // row m+8
            }
        }

        if (mt < 15) {
            CP_WAIT0();
            __syncthreads();
        }
    }
}

// ---------------------------------------------------------------------------
// Kernel 2: noise similarity (unchanged)
// ---------------------------------------------------------------------------
__global__ __launch_bounds__(256)
void noise_sim_kernel(const float* __restrict__ features,
                      const float* __restrict__ memory,
                      float* __restrict__ out) {
    __shared__ float ns[BATCH * NUM_CLUT][MESH_DIM];

    const int c = blockIdx.y;
    const int j = blockIdx.x * 256 + threadIdx.x;

    for (int idx = threadIdx.x; idx < BATCH * NUM_CLUT * MESH_DIM; idx += 256) {
        const int r = idx >> 7;
        const int v = idx & 127;
        const int bb = r / NUM_CLUT;
        const int kk = r % NUM_CLUT;
        ns[r][v] = features[(size_t)(bb * FEAT_ROWS + MAX_N + kk) * MESH_DIM + v];
    }
    __syncthreads();

    float acc[BATCH * NUM_CLUT];
#pragma unroll
    for (int r = 0; r < BATCH * NUM_CLUT; r++) acc[r] = 0.0f;

    const float* mp = memory + (size_t)c * (MESH_DIM * MAX_N) + j;
#pragma unroll 4
    for (int v = 0; v < MESH_DIM; v++) {
        const float mv = mp[(size_t)v * MAX_N];
#pragma unroll
        for (int r = 0; r < BATCH * NUM_CLUT; r++) acc[r] += ns[r][v] * mv;
    }

#pragma unroll
    for (int r = 0; r < BATCH * NUM_CLUT; r++)
        out[(size_t)r * CJ + c * MAX_N + j] = acc[r];
}

// ---------------------------------------------------------------------------
// Kernel 3: memory update (visible is int32)
// ---------------------------------------------------------------------------
__global__ __launch_bounds__(256)
void mem_update_kernel(const float* __restrict__ features,
                       const int* __restrict__ visible,
                       const int* __restrict__ label,
                       const float* __restrict__ memory,
                       float* __restrict__ out) {
    __shared__ float tile[MESH_DIM][32];
    __shared__ float ssqs[8][32];

    const int c  = blockIdx.y;
    const int j0 = blockIdx.x * 32;
    const int t  = threadIdx.x;
    const int jx = t & 31;
    const int vy = t >> 5;
    const int j  = j0 + jx;

    int lbl[BATCH];
#pragma unroll
    for (int bb = 0; bb < BATCH; bb++) lbl[bb] = label[bb];

    int cnt = 0;
#pragma unroll
    for (int bb = 0; bb < BATCH; bb++) cnt += (lbl[bb] == c) ? 1 : 0;

    float w[BATCH];
    const float inv = (cnt > 0) ? (1.0f / (float)cnt) : 0.0f;
#pragma unroll
    for (int bb = 0; bb < BATCH; bb++)
        w[bb] = (lbl[bb] == c && visible[bb * MAX_N + j] != 0) ? inv : 0.0f;

    float ssq = 0.0f;
#pragma unroll
    for (int vv = 0; vv < 16; vv++) {
        const int v = vy * 16 + vv;
        const float mm = memory[(size_t)c * (MESH_DIM * MAX_N) + (size_t)v * MAX_N + j];
        float val;
        if (cnt == 0) {
            val = mm;
        } else {
            float s = 0.0f;
#pragma unroll
            for (int bb = 0; bb < BATCH; bb++)
                s += w[bb] * features[(size_t)(bb * FEAT_ROWS + j) * MESH_DIM + v];
            val = 0.9f * mm + 0.1f * s;
        }
        tile[v][jx] = val;
        ssq += val * val;
    }
    ssqs[vy][jx] = ssq;
    __syncthreads();

    float tot = 0.0f;
#pragma unroll
    for (int y = 0; y < 8; y++) tot += ssqs[y][jx];
    const float rn = 1.0f / fmaxf(sqrtf(tot), 1e-12f);

#pragma unroll
    for (int vv = 0; vv < 16; vv++) {
        const int v = vy * 16 + vv;
        out[(size_t)c * (MESH_DIM * MAX_N) + (size_t)v * MAX_N + j] = tile[v][jx] * rn;
    }
}

// ---------------------------------------------------------------------------
// Kernel 4: clutter bank update (unchanged)
// ---------------------------------------------------------------------------
__global__ __launch_bounds__(128)
void clutter_kernel(const float* __restrict__ clutter,
                    const float* __restrict__ features,
                    const int* __restrict__ lru,
                    float* __restrict__ out) {
    const int n = blockIdx.x * 128 + threadIdx.x;
    const int new_lru = (lru[0] + 1) % (BANK_SIZE / BATCH);
    const int start = new_lru * (NUM_CLUT * BATCH);

    const bool upd = (n >= start) && (n < start + NUM_CLUT * BATCH);
    const int mm = n - start;
    const int bb = upd ? (mm / NUM_CLUT) : 0;
    const int kk = upd ? (mm % NUM_CLUT) : 0;
    const float* nsrc = features + (size_t)(bb * FEAT_ROWS + MAX_N + kk) * MESH_DIM;

    float ssq = 0.0f;
#pragma unroll 4
    for (int v = 0; v < MESH_DIM; v++) {
        const float val = upd ? nsrc[v] : clutter[(size_t)v * NCLUT_TOT + n];
        ssq += val * val;
    }
    const float rn = 1.0f / fmaxf(sqrtf(ssq), 1e-12f);

#pragma unroll 4
    for (int v = 0; v < MESH_DIM; v++) {
        const float val = upd ? nsrc[v] : clutter[(size_t)v * NCLUT_TOT + n];
        out[(size_t)v * NCLUT_TOT + n] = val * rn;
    }
}

// ---------------------------------------------------------------------------
// Launcher
// ---------------------------------------------------------------------------
#define GEMM_DSMEM (3 * TILE_FLOATS * 4)   // 208,896 bytes

extern "C" void kernel_launch(void* const* d_in, const int* in_sizes, int n_in,
                              void* d_out, int out_size) {
    const float* features = (const float*)d_in[0];
    const int*   visible  = (const int*)d_in[1];
    const int*   label    = (const int*)d_in[2];
    const float* memory   = (const float*)d_in[3];
    const float* clutter  = (const float*)d_in[4];
    const int*   lru      = (const int*)d_in[5];

    float* out = (float*)d_out;
    float* out_sim  = out + OUT_SIM_OFF;
    float* out_nsim = out + OUT_NSIM_OFF;
    float* out_mem  = out + OUT_MEM_OFF;
    float* out_cb   = out + OUT_CB_OFF;

    cudaFuncSetAttribute(sim_gemm_tf32_kernel,
                         cudaFuncAttributeMaxDynamicSharedMemorySize, GEMM_DSMEM);

    // tf32 conversions (feed the mma.sync GEMM)
    convert_a_kernel<<<256, 256>>>(features);
    convert_w_kernel<<<1024 + NCLUT_TOT / 32, 256>>>(memory, clutter);

    // Independent small kernels
    noise_sim_kernel<<<dim3(2, N_CLASSES), 256>>>(features, memory, out_nsim);
    mem_update_kernel<<<dim3(MAX_N / 32, N_CLASSES), 256>>>(features, visible, label,
                                                            memory, out_mem);
    clutter_kernel<<<NCLUT_TOT / 128, 128>>>(clutter, features, lru, out_cb);

    // Main similarity GEMM (tf32 mma.sync)
    sim_gemm_tf32_kernel<<<NTOT / 128, 256, GEMM_DSMEM>>>(out_sim);
}

// round 5
// speedup vs baseline: 2.6391x; 1.1534x over previous
#include <cuda_runtime.h>
#include <cuda_bf16.h>
#include <cstdint>

// Problem constants
#define MAX_N     512
#define N_CLASSES 64
#define MESH_DIM  128
#define NUM_CLUT  5
#define BANK_SIZE 4096
#define BATCH     4
#define FEAT_ROWS (MAX_N + NUM_CLUT)          // 517
#define CJ        (N_CLASSES * MAX_N)          // 32768
#define NCLUT_TOT (NUM_CLUT * BANK_SIZE)       // 20480
#define NTOT      (CJ + NCLUT_TOT)             // 53248
#define M_TOT     (BATCH * MAX_N)              // 2048

// Output offsets (element counts)
#define OUT_SIM_OFF   0ULL
#define OUT_SIM_SZ    ((unsigned long long)BATCH * MAX_N * NTOT)
#define OUT_NSIM_OFF  (OUT_SIM_OFF + OUT_SIM_SZ)
#define OUT_NSIM_SZ   ((unsigned long long)BATCH * NUM_CLUT * CJ)
#define OUT_MEM_OFF   (OUT_NSIM_OFF + OUT_NSIM_SZ)
#define OUT_MEM_SZ    ((unsigned long long)N_CLASSES * MESH_DIM * MAX_N)
#define OUT_CB_OFF    (OUT_MEM_OFF + OUT_MEM_SZ)

// ---------------------------------------------------------------------------
// tf32 scratch (device globals — allocation-free rule).
// Layout: row-major [m][k] / [n][k], k permuted within 8-blocks so that
// logical cols (t, t+4) sit at positions (2t, 2t+1)  -> fragment LDS.64.
// ---------------------------------------------------------------------------
__device__ __align__(16) float g_A [(size_t)M_TOT * MESH_DIM];   // 1 MB
__device__ __align__(16) float g_Wt[(size_t)NTOT  * MESH_DIM];   // 27.25 MB

__device__ __host__ __forceinline__ int kpos(int k) {
    return (k & ~7) | (((k & 3) << 1) | ((k >> 2) & 1));
}

__device__ __forceinline__ float to_tf32(float x) {
    uint32_t u;
    asm("cvt.rna.tf32.f32 %0, %1;" : "=r"(u) : "f"(x));
    return __uint_as_float(u);
}

__device__ __forceinline__ uint32_t smem_u32(const void* p) {
    uint32_t a;
    asm("{ .reg .u64 t; cvta.to.shared.u64 t, %1; cvt.u32.u64 %0, t; }" : "=r"(a) : "l"(p));
    return a;
}

#define CP_ASYNC16(saddr, gptr) \
    asm volatile("cp.async.cg.shared.global [%0], [%1], 16;" :: "r"(saddr), "l"(gptr))
#define CP_COMMIT() asm volatile("cp.async.commit_group;")
#define CP_WAIT0()  asm volatile("cp.async.wait_group 0;")

// m16n8k8 tf32 MMA (sm_80 baseline — works at compute_103)
__device__ __forceinline__ void mma_tf32(float& c0, float& c1, float& c2, float& c3,
                                         uint32_t a0, uint32_t a1, uint32_t a2, uint32_t a3,
                                         uint32_t b0, uint32_t b1) {
    asm volatile(
        "mma.sync.aligned.m16n8k8.row.col.f32.tf32.tf32.f32 "
        "{%0,%1,%2,%3}, {%4,%5,%6,%7}, {%8,%9}, {%0,%1,%2,%3};"
        : "+f"(c0), "+f"(c1), "+f"(c2), "+f"(c3)
        : "r"(a0), "r"(a1), "r"(a2), "r"(a3), "r"(b0), "r"(b1));
}

// ---------------------------------------------------------------------------
// Fused conversion kernel (launch #1):
//   blocks [0,64)          : A -> tf32 k-permuted
//   blocks [64, 64+1664)   : W transpose -> [n][k] tf32 k-permuted (float4 STG)
// ---------------------------------------------------------------------------
__global__ __launch_bounds__(256)
void convert_fused_kernel(const float* __restrict__ features,
                          const float* __restrict__ memory,
                          const float* __restrict__ clutter) {
    if (blockIdx.x < 64) {
        // ---- A conversion: 262144 elems over 64 blocks ----
        for (int idx = blockIdx.x * 4096 + threadIdx.x; idx < (blockIdx.x + 1) * 4096 * 1;
             idx += 256) { }
        const int base = blockIdx.x * 4096;
        for (int e = threadIdx.x; e < 4096; e += 256) {
            const int idx = base + e;
            const int m = idx >> 7;
            const int k = idx & 127;
            const int b = m >> 9;
            const int i = m & 511;
            const float x = features[(size_t)(b * FEAT_ROWS + i) * MESH_DIM + k];
            g_A[((size_t)m << 7) | kpos(k)] = to_tf32(x);
        }
        return;
    }

    // ---- W transpose+convert ----
    __shared__ float tile[MESH_DIM][33];
    const int blk = blockIdx.x - 64;
    const float* src;
    int ld, nbase;
    if (blk < 1024) {       // memory part: 64 classes x 16 j-tiles
        const int c  = blk >> 4;
        const int j0 = (blk & 15) * 32;
        src   = memory + (size_t)c * (MESH_DIM * MAX_N) + j0;
        ld    = MAX_N;
        nbase = c * MAX_N + j0;
    } else {                // clutter part: 640 n-tiles
        const int n0 = (blk - 1024) * 32;
        src   = clutter + n0;
        ld    = NCLUT_TOT;
        nbase = CJ + n0;
    }

    for (int e = threadIdx.x; e < MESH_DIM * 32; e += 256) {
        const int k  = e >> 5;
        const int jx = e & 31;
        tile[k][jx] = src[(size_t)k * ld + jx];
    }
    __syncthreads();

    const int jx = threadIdx.x >> 3;         // 0..31
    const int kc = (threadIdx.x & 7) * 16;   // 0..112
    float* dst = &g_Wt[(size_t)(nbase + jx) * MESH_DIM + kc];
    // pos p in an 8-block holds logical k: 0,4,1,5,2,6,3,7
    float4 f0, f1, f2, f3;
    f0.x = to_tf32(tile[kc + 0][jx]);  f0.y = to_tf32(tile[kc + 4][jx]);
    f0.z = to_tf32(tile[kc + 1][jx]);  f0.w = to_tf32(tile[kc + 5][jx]);
    f1.x = to_tf32(tile[kc + 2][jx]);  f1.y = to_tf32(tile[kc + 6][jx]);
    f1.z = to_tf32(tile[kc + 3][jx]);  f1.w = to_tf32(tile[kc + 7][jx]);
    f2.x = to_tf32(tile[kc + 8][jx]);  f2.y = to_tf32(tile[kc + 12][jx]);
    f2.z = to_tf32(tile[kc + 9][jx]);  f2.w = to_tf32(tile[kc + 13][jx]);
    f3.x = to_tf32(tile[kc + 10][jx]); f3.y = to_tf32(tile[kc + 14][jx]);
    f3.z = to_tf32(tile[kc + 11][jx]); f3.w = to_tf32(tile[kc + 15][jx]);
    reinterpret_cast<float4*>(dst)[0] = f0;
    reinterpret_cast<float4*>(dst)[1] = f1;
    reinterpret_cast<float4*>(dst)[2] = f2;
    reinterpret_cast<float4*>(dst)[3] = f3;
}

// ---------------------------------------------------------------------------
// Fused aux kernel (launch #2): noise_sim + mem_update + clutter
//   blocks [0,128)        : noise similarity   (c = b>>1, jtile = b&1)
//   blocks [128,384)      : memory update      (c = (b-128)>>2, jtile 128-wide)
//   blocks [384,464)      : clutter bank       (n-tile 256-wide)
// ---------------------------------------------------------------------------
__global__ __launch_bounds__(256)
void aux_fused_kernel(const float* __restrict__ features,
                      const int* __restrict__ visible,
                      const int* __restrict__ label,
                      const float* __restrict__ memory,
                      const float* __restrict__ clutter,
                      const int* __restrict__ lru,
                      float* __restrict__ out_nsim,
                      float* __restrict__ out_mem,
                      float* __restrict__ out_cb) {
    const int bx = blockIdx.x;

    if (bx < 128) {
        // ================= noise similarity =================
        __shared__ float ns[BATCH * NUM_CLUT][MESH_DIM];
        const int c = bx >> 1;
        const int j = (bx & 1) * 256 + threadIdx.x;

        for (int idx = threadIdx.x; idx < BATCH * NUM_CLUT * MESH_DIM; idx += 256) {
            const int r = idx >> 7;
            const int v = idx & 127;
            const int bb = r / NUM_CLUT;
            const int kk = r % NUM_CLUT;
            ns[r][v] = features[(size_t)(bb * FEAT_ROWS + MAX_N + kk) * MESH_DIM + v];
        }
        __syncthreads();

        float acc[BATCH * NUM_CLUT];
#pragma unroll
        for (int r = 0; r < BATCH * NUM_CLUT; r++) acc[r] = 0.0f;

        const float* mp = memory + (size_t)c * (MESH_DIM * MAX_N) + j;
#pragma unroll 4
        for (int v = 0; v < MESH_DIM; v++) {
            const float mv = mp[(size_t)v * MAX_N];
#pragma unroll
            for (int r = 0; r < BATCH * NUM_CLUT; r++) acc[r] += ns[r][v] * mv;
        }
#pragma unroll
        for (int r = 0; r < BATCH * NUM_CLUT; r++)
            out_nsim[(size_t)r * CJ + c * MAX_N + j] = acc[r];
        return;
    }

    if (bx < 384) {
        // ================= memory update (float4 over j) =================
        __shared__ float4 ssqs[8][32];
        const int blk = bx - 128;
        const int c   = blk >> 2;
        const int j0  = (blk & 3) * 128;
        const int t   = threadIdx.x;
        const int jx  = t & 31;
        const int vy  = t >> 5;               // 0..7
        const int j   = j0 + jx * 4;

        int lbl[BATCH];
#pragma unroll
        for (int bb = 0; bb < BATCH; bb++) lbl[bb] = label[bb];
        int cnt = 0;
#pragma unroll
        for (int bb = 0; bb < BATCH; bb++) cnt += (lbl[bb] == c) ? 1 : 0;
        const float inv = (cnt > 0) ? (1.0f / (float)cnt) : 0.0f;

        float w[BATCH][4];
#pragma unroll
        for (int bb = 0; bb < BATCH; bb++)
#pragma unroll
            for (int d = 0; d < 4; d++)
                w[bb][d] = (lbl[bb] == c && visible[bb * MAX_N + j + d] != 0) ? inv : 0.0f;

        const float* mrow = memory + (size_t)c * (MESH_DIM * MAX_N) + j;
        float4 vals[16];
        float4 ssq = make_float4(0.f, 0.f, 0.f, 0.f);
#pragma unroll
        for (int vv = 0; vv < 16; vv++) {
            const int v = vy * 16 + vv;
            float4 m = *reinterpret_cast<const float4*>(mrow + (size_t)v * MAX_N);
            if (cnt > 0) {
                float s[4];
#pragma unroll
                for (int d = 0; d < 4; d++) {
                    s[d] = 0.0f;
#pragma unroll
                    for (int bb = 0; bb < BATCH; bb++)
                        s[d] += w[bb][d] *
                                features[(size_t)(bb * FEAT_ROWS + j + d) * MESH_DIM + v];
                }
                m.x = 0.9f * m.x + 0.1f * s[0];
                m.y = 0.9f * m.y + 0.1f * s[1];
                m.z = 0.9f * m.z + 0.1f * s[2];
                m.w = 0.9f * m.w + 0.1f * s[3];
            }
            vals[vv] = m;
            ssq.x += m.x * m.x;  ssq.y += m.y * m.y;
            ssq.z += m.z * m.z;  ssq.w += m.w * m.w;
        }
        ssqs[vy][jx] = ssq;
        __syncthreads();

        float4 tot = make_float4(0.f, 0.f, 0.f, 0.f);
#pragma unroll
        for (int y = 0; y < 8; y++) {
            const float4 q = ssqs[y][jx];
            tot.x += q.x; tot.y += q.y; tot.z += q.z; tot.w += q.w;
        }
        float4 rn;
        rn.x = 1.0f / fmaxf(sqrtf(tot.x), 1e-12f);
        rn.y = 1.0f / fmaxf(sqrtf(tot.y), 1e-12f);
        rn.z = 1.0f / fmaxf(sqrtf(tot.z), 1e-12f);
        rn.w = 1.0f / fmaxf(sqrtf(tot.w), 1e-12f);

        float* orow = out_mem + (size_t)c * (MESH_DIM * MAX_N) + j;
#pragma unroll
        for (int vv = 0; vv < 16; vv++) {
            const int v = vy * 16 + vv;
            float4 m = vals[vv];
            m.x *= rn.x; m.y *= rn.y; m.z *= rn.z; m.w *= rn.w;
            *reinterpret_cast<float4*>(orow + (size_t)v * MAX_N) = m;
        }
        return;
    }

    // ================= clutter bank update =================
    {
        const int n = (bx - 384) * 256 + threadIdx.x;   // 0..20479
        const int new_lru = (lru[0] + 1) % (BANK_SIZE / BATCH);
        const int start = new_lru * (NUM_CLUT * BATCH);

        const bool upd = (n >= start) && (n < start + NUM_CLUT * BATCH);
        const int mm = n - start;
        const int bb = upd ? (mm / NUM_CLUT) : 0;
        const int kk = upd ? (mm % NUM_CLUT) : 0;
        const float* nsrc = features + (size_t)(bb * FEAT_ROWS + MAX_N + kk) * MESH_DIM;

        float ssq = 0.0f;
#pragma unroll 8
        for (int v = 0; v < MESH_DIM; v++) {
            const float val = upd ? nsrc[v] : clutter[(size_t)v * NCLUT_TOT + n];
            ssq += val * val;
        }
        const float rn = 1.0f / fmaxf(sqrtf(ssq), 1e-12f);

#pragma unroll 8
        for (int v = 0; v < MESH_DIM; v++) {
            const float val = upd ? nsrc[v] : clutter[(size_t)v * NCLUT_TOT + n];
            out_cb[(size_t)v * NCLUT_TOT + n] = val * rn;
        }
    }
}

// ---------------------------------------------------------------------------
// tf32 mma.sync GEMM (launch #3 — unchanged from R4).
// ---------------------------------------------------------------------------
#define LDK 136
#define TILE_FLOATS (128 * LDK)

__global__ __launch_bounds__(256)
void sim_gemm_tf32_kernel(float* __restrict__ out) {
    extern __shared__ float smem[];
    float* Ws  = smem;                     // [128][136]
    float* As0 = smem + TILE_FLOATS;
    float* As1 = As0 + TILE_FLOATS;

    const int tid  = threadIdx.x;
    const int wid  = tid >> 5;
    const int lane = tid & 31;
    const int g    = lane >> 2;            // 0..7
    const int tg   = lane & 3;             // 0..3
    const int wm   = (wid >> 2) * 64;      // 0 / 64
    const int wn   = (wid & 3) * 32;       // 0..96
    const int n0   = blockIdx.x * 128;

    // ---- initial loads: W tile + A tile 0 (cp.async) ----
    {
        const float* wsrc = g_Wt + (size_t)n0 * MESH_DIM;
        const uint32_t wbase = smem_u32(Ws);
        const float* asrc = g_A;
        const uint32_t abase = smem_u32(As0);
        for (int c = tid; c < 4096; c += 256) {
            const int row = c >> 5, cid = c & 31;
            CP_ASYNC16(wbase + (uint32_t)(row * LDK + cid * 4) * 4,
                       wsrc + (size_t)row * MESH_DIM + cid * 4);
            CP_ASYNC16(abase + (uint32_t)(row * LDK + cid * 4) * 4,
                       asrc + (size_t)row * MESH_DIM + cid * 4);
        }
        CP_COMMIT();
        CP_WAIT0();
    }
    __syncthreads();

    float* bufs[2] = { As0, As1 };

    for (int mt = 0; mt < 16; mt++) {
        const float* cur = bufs[mt & 1];

        if (mt < 15) {
            const float* asrc = g_A + ((size_t)(mt + 1) * 128) * MESH_DIM;
            const uint32_t abase = smem_u32(bufs[(mt + 1) & 1]);
            for (int c = tid; c < 4096; c += 256) {
                const int row = c >> 5, cid = c & 31;
                CP_ASYNC16(abase + (uint32_t)(row * LDK + cid * 4) * 4,
                           asrc + (size_t)row * MESH_DIM + cid * 4);
            }
            CP_COMMIT();
        }

        float acc[4][4][4];
#pragma unroll
        for (int mi = 0; mi < 4; mi++)
#pragma unroll
            for (int ni = 0; ni < 4; ni++)
#pragma unroll
                for (int r = 0; r < 4; r++) acc[mi][ni][r] = 0.0f;

#pragma unroll
        for (int ks = 0; ks < 16; ks++) {
            const int colb = ks * 8 + 2 * tg;

            uint32_t a0[4], a1[4], a2[4], a3[4];
#pragma unroll
            for (int mi = 0; mi < 4; mi++) {
                const float* p = &cur[(wm + mi * 16 + g) * LDK + colb];
                const float2 lo = *reinterpret_cast<const float2*>(p);
                const float2 hi = *reinterpret_cast<const float2*>(p + 8 * LDK);
                a0[mi] = __float_as_uint(lo.x);
                a2[mi] = __float_as_uint(lo.y);
                a1[mi] = __float_as_uint(hi.x);
                a3[mi] = __float_as_uint(hi.y);
            }
            uint32_t b0[4], b1[4];
#pragma unroll
            for (int ni = 0; ni < 4; ni++) {
                const float2 bv = *reinterpret_cast<const float2*>(
                    &Ws[(wn + ni * 8 + g) * LDK + colb]);
                b0[ni] = __float_as_uint(bv.x);
                b1[ni] = __float_as_uint(bv.y);
            }
#pragma unroll
            for (int mi = 0; mi < 4; mi++)
#pragma unroll
                for (int ni = 0; ni < 4; ni++)
                    mma_tf32(acc[mi][ni][0], acc[mi][ni][1],
                             acc[mi][ni][2], acc[mi][ni][3],
                             a0[mi], a1[mi], a2[mi], a3[mi],
                             b0[ni], b1[ni]);
        }

        // ---- store D tile ----
#pragma unroll
        for (int mi = 0; mi < 4; mi++) {
            const size_t m = (size_t)(mt * 128 + wm + mi * 16 + g);
#pragma unroll
            for (int ni = 0; ni < 4; ni++) {
                float* o = out + m * NTOT + (n0 + wn + ni * 8 + 2 * tg);
                float2 v0; v0.x = acc[mi][ni][0]; v0.y = acc[mi][ni][1];
                float2 v1; v1.x = acc[mi][ni][2]; v1.y = acc[mi][ni][3];
                *reinterpret_cast<float2*>(o)            = v0;
                *reinterpret_cast<float2*>(o + 8 * NTOT) = v1;
            }
        }

        if (mt < 15) {
            CP_WAIT0();
            __syncthreads();
        }
    }
}

// ---------------------------------------------------------------------------
// Launcher — exactly 3 kernels so ncu (-s 5 -c 1) lands on the GEMM.
// ---------------------------------------------------------------------------
#define GEMM_DSMEM (3 * TILE_FLOATS * 4)   // 208,896 bytes

extern "C" void kernel_launch(void* const* d_in, const int* in_sizes, int n_in,
                              void* d_out, int out_size) {
    const float* features = (const float*)d_in[0];
    const int*   visible  = (const int*)d_in[1];
    const int*   label    = (const int*)d_in[2];
    const float* memory   = (const float*)d_in[3];
    const float* clutter  = (const float*)d_in[4];
    const int*   lru      = (const int*)d_in[5];

    float* out = (float*)d_out;
    float* out_sim  = out + OUT_SIM_OFF;
    float* out_nsim = out + OUT_NSIM_OFF;
    float* out_mem  = out + OUT_MEM_OFF;
    float* out_cb   = out + OUT_CB_OFF;

    cudaFuncSetAttribute(sim_gemm_tf32_kernel,
                         cudaFuncAttributeMaxDynamicSharedMemorySize, GEMM_DSMEM);

    convert_fused_kernel<<<64 + 1024 + NCLUT_TOT / 32, 256>>>(features, memory, clutter);
    aux_fused_kernel<<<128 + 256 + NCLUT_TOT / 256, 256>>>(features, visible, label,
                                                           memory, clutter, lru,
                                                           out_nsim, out_mem, out_cb);
    sim_gemm_tf32_kernel<<<NTOT / 128, 256, GEMM_DSMEM>>>(out_sim);
}

// round 6
// speedup vs baseline: 2.8063x; 1.0634x over previous
#include <cuda_runtime.h>
#include <cuda_bf16.h>
#include <cstdint>

// Problem constants
#define MAX_N     512
#define N_CLASSES 64
#define MESH_DIM  128
#define NUM_CLUT  5
#define BANK_SIZE 4096
#define BATCH     4
#define FEAT_ROWS (MAX_N + NUM_CLUT)          // 517
#define CJ        (N_CLASSES * MAX_N)          // 32768
#define NCLUT_TOT (NUM_CLUT * BANK_SIZE)       // 20480
#define NTOT      (CJ + NCLUT_TOT)             // 53248
#define M_TOT     (BATCH * MAX_N)              // 2048

// Output offsets (element counts)
#define OUT_SIM_OFF   0ULL
#define OUT_SIM_SZ    ((unsigned long long)BATCH * MAX_N * NTOT)
#define OUT_NSIM_OFF  (OUT_SIM_OFF + OUT_SIM_SZ)
#define OUT_NSIM_SZ   ((unsigned long long)BATCH * NUM_CLUT * CJ)
#define OUT_MEM_OFF   (OUT_NSIM_OFF + OUT_NSIM_SZ)
#define OUT_MEM_SZ    ((unsigned long long)N_CLASSES * MESH_DIM * MAX_N)
#define OUT_CB_OFF    (OUT_MEM_OFF + OUT_MEM_SZ)

// ---------------------------------------------------------------------------
// tf32 A scratch (device global — allocation-free rule).
// Row-major [m][k], k permuted within 8-blocks: pos 2t,2t+1 hold k=t,t+4
// so A fragment pairs (k, k+4) are one LDS.64.
// ---------------------------------------------------------------------------
__device__ __align__(16) float g_A[(size_t)M_TOT * MESH_DIM];   // 1 MB

__device__ __forceinline__ int kpos(int k) {
    return (k & ~7) | (((k & 3) << 1) | ((k >> 2) & 1));
}

__device__ __forceinline__ float to_tf32(float x) {
    uint32_t u;
    asm("cvt.rna.tf32.f32 %0, %1;" : "=r"(u) : "f"(x));
    return __uint_as_float(u);
}

__device__ __forceinline__ uint32_t smem_u32(const void* p) {
    uint32_t a;
    asm("{ .reg .u64 t; cvta.to.shared.u64 t, %1; cvt.u32.u64 %0, t; }" : "=r"(a) : "l"(p));
    return a;
}

#define CP_ASYNC16(saddr, gptr) \
    asm volatile("cp.async.cg.shared.global [%0], [%1], 16;" :: "r"(saddr), "l"(gptr))
#define CP_COMMIT() asm volatile("cp.async.commit_group;")
#define CP_WAIT0()  asm volatile("cp.async.wait_group 0;")

// m16n8k8 tf32 MMA (sm_80 baseline — works at compute_103)
__device__ __forceinline__ void mma_tf32(float& c0, float& c1, float& c2, float& c3,
                                         uint32_t a0, uint32_t a1, uint32_t a2, uint32_t a3,
                                         uint32_t b0, uint32_t b1) {
    asm volatile(
        "mma.sync.aligned.m16n8k8.row.col.f32.tf32.tf32.f32 "
        "{%0,%1,%2,%3}, {%4,%5,%6,%7}, {%8,%9}, {%0,%1,%2,%3};"
        : "+f"(c0), "+f"(c1), "+f"(c2), "+f"(c3)
        : "r"(a0), "r"(a1), "r"(a2), "r"(a3), "r"(b0), "r"(b1));
}

// ---------------------------------------------------------------------------
// Launch #1 — fused prep: A tf32 convert + noise_sim + mem_update + clutter.
//   blocks [0,64)     : A convert
//   blocks [64,192)   : noise similarity
//   blocks [192,448)  : memory update
//   blocks [448,528)  : clutter bank
// ---------------------------------------------------------------------------
__global__ __launch_bounds__(256)
void prep_fused_kernel(const float* __restrict__ features,
                       const int* __restrict__ visible,
                       const int* __restrict__ label,
                       const float* __restrict__ memory,
                       const float* __restrict__ clutter,
                       const int* __restrict__ lru,
                       float* __restrict__ out_nsim,
                       float* __restrict__ out_mem,
                       float* __restrict__ out_cb) {
    const int bx = blockIdx.x;

    if (bx < 64) {
        // ================= A conversion =================
        const int base = bx * 4096;
        for (int e = threadIdx.x; e < 4096; e += 256) {
            const int idx = base + e;
            const int m = idx >> 7;
            const int k = idx & 127;
            const int b = m >> 9;
            const int i = m & 511;
            const float x = features[(size_t)(b * FEAT_ROWS + i) * MESH_DIM + k];
            g_A[((size_t)m << 7) | kpos(k)] = to_tf32(x);
        }
        return;
    }

    if (bx < 192) {
        // ================= noise similarity =================
        __shared__ float ns[BATCH * NUM_CLUT][MESH_DIM];
        const int blk = bx - 64;
        const int c = blk >> 1;
        const int j = (blk & 1) * 256 + threadIdx.x;

        for (int idx = threadIdx.x; idx < BATCH * NUM_CLUT * MESH_DIM; idx += 256) {
            const int r = idx >> 7;
            const int v = idx & 127;
            const int bb = r / NUM_CLUT;
            const int kk = r % NUM_CLUT;
            ns[r][v] = features[(size_t)(bb * FEAT_ROWS + MAX_N + kk) * MESH_DIM + v];
        }
        __syncthreads();

        float acc[BATCH * NUM_CLUT];
#pragma unroll
        for (int r = 0; r < BATCH * NUM_CLUT; r++) acc[r] = 0.0f;

        const float* mp = memory + (size_t)c * (MESH_DIM * MAX_N) + j;
#pragma unroll 4
        for (int v = 0; v < MESH_DIM; v++) {
            const float mv = mp[(size_t)v * MAX_N];
#pragma unroll
            for (int r = 0; r < BATCH * NUM_CLUT; r++) acc[r] += ns[r][v] * mv;
        }
#pragma unroll
        for (int r = 0; r < BATCH * NUM_CLUT; r++)
            out_nsim[(size_t)r * CJ + c * MAX_N + j] = acc[r];
        return;
    }

    if (bx < 448) {
        // ================= memory update (float4 over j) =================
        __shared__ float4 ssqs[8][32];
        const int blk = bx - 192;
        const int c   = blk >> 2;
        const int j0  = (blk & 3) * 128;
        const int t   = threadIdx.x;
        const int jx  = t & 31;
        const int vy  = t >> 5;               // 0..7
        const int j   = j0 + jx * 4;

        int lbl[BATCH];
#pragma unroll
        for (int bb = 0; bb < BATCH; bb++) lbl[bb] = label[bb];
        int cnt = 0;
#pragma unroll
        for (int bb = 0; bb < BATCH; bb++) cnt += (lbl[bb] == c) ? 1 : 0;
        const float inv = (cnt > 0) ? (1.0f / (float)cnt) : 0.0f;

        float w[BATCH][4];
#pragma unroll
        for (int bb = 0; bb < BATCH; bb++)
#pragma unroll
            for (int d = 0; d < 4; d++)
                w[bb][d] = (lbl[bb] == c && visible[bb * MAX_N + j + d] != 0) ? inv : 0.0f;

        const float* mrow = memory + (size_t)c * (MESH_DIM * MAX_N) + j;
        float4 vals[16];
        float4 ssq = make_float4(0.f, 0.f, 0.f, 0.f);
#pragma unroll
        for (int vv = 0; vv < 16; vv++) {
            const int v = vy * 16 + vv;
            float4 m = *reinterpret_cast<const float4*>(mrow + (size_t)v * MAX_N);
            if (cnt > 0) {
                float s[4];
#pragma unroll
                for (int d = 0; d < 4; d++) {
                    s[d] = 0.0f;
#pragma unroll
                    for (int bb = 0; bb < BATCH; bb++)
                        s[d] += w[bb][d] *
                                features[(size_t)(bb * FEAT_ROWS + j + d) * MESH_DIM + v];
                }
                m.x = 0.9f * m.x + 0.1f * s[0];
                m.y = 0.9f * m.y + 0.1f * s[1];
                m.z = 0.9f * m.z + 0.1f * s[2];
                m.w = 0.9f * m.w + 0.1f * s[3];
            }
            vals[vv] = m;
            ssq.x += m.x * m.x;  ssq.y += m.y * m.y;
            ssq.z += m.z * m.z;  ssq.w += m.w * m.w;
        }
        ssqs[vy][jx] = ssq;
        __syncthreads();

        float4 tot = make_float4(0.f, 0.f, 0.f, 0.f);
#pragma unroll
        for (int y = 0; y < 8; y++) {
            const float4 q = ssqs[y][jx];
            tot.x += q.x; tot.y += q.y; tot.z += q.z; tot.w += q.w;
        }
        float4 rn;
        rn.x = 1.0f / fmaxf(sqrtf(tot.x), 1e-12f);
        rn.y = 1.0f / fmaxf(sqrtf(tot.y), 1e-12f);
        rn.z = 1.0f / fmaxf(sqrtf(tot.z), 1e-12f);
        rn.w = 1.0f / fmaxf(sqrtf(tot.w), 1e-12f);

        float* orow = out_mem + (size_t)c * (MESH_DIM * MAX_N) + j;
#pragma unroll
        for (int vv = 0; vv < 16; vv++) {
            const int v = vy * 16 + vv;
            float4 m = vals[vv];
            m.x *= rn.x; m.y *= rn.y; m.z *= rn.z; m.w *= rn.w;
            *reinterpret_cast<float4*>(orow + (size_t)v * MAX_N) = m;
        }
        return;
    }

    // ================= clutter bank update =================
    {
        const int n = (bx - 448) * 256 + threadIdx.x;   // 0..20479
        const int new_lru = (lru[0] + 1) % (BANK_SIZE / BATCH);
        const int start = new_lru * (NUM_CLUT * BATCH);

        const bool upd = (n >= start) && (n < start + NUM_CLUT * BATCH);
        const int mm = n - start;
        const int bb = upd ? (mm / NUM_CLUT) : 0;
        const int kk = upd ? (mm % NUM_CLUT) : 0;
        const float* nsrc = features + (size_t)(bb * FEAT_ROWS + MAX_N + kk) * MESH_DIM;

        float ssq = 0.0f;
#pragma unroll 8
        for (int v = 0; v < MESH_DIM; v++) {
            const float val = upd ? nsrc[v] : clutter[(size_t)v * NCLUT_TOT + n];
            ssq += val * val;
        }
        const float rn = 1.0f / fmaxf(sqrtf(ssq), 1e-12f);

#pragma unroll 8
        for (int v = 0; v < MESH_DIM; v++) {
            const float val = upd ? nsrc[v] : clutter[(size_t)v * NCLUT_TOT + n];
            out_cb[(size_t)v * NCLUT_TOT + n] = val * rn;
        }
    }
}

// ---------------------------------------------------------------------------
// Launch #2 — tf32 mma.sync GEMM.
//   out[m][n] = A[m][:128] . W[:][n]
// W slice loaded RAW from memory/clutter (coalesced rows) into smem [k][n]
// (ld 136), converted to tf32 in-smem once per CTA. A 128x128 m-tiles
// (pre-converted, k-permuted) double-buffered via cp.async. 8 warps = 2m x 4n,
// warp tile 64m x 32n. B frags via 2x LDS.32 (banks 8*tg+g — conflict-free).
// ---------------------------------------------------------------------------
#define LDK 136
#define TILE_FLOATS (128 * LDK)

__global__ __launch_bounds__(256)
void sim_gemm_tf32_kernel(const float* __restrict__ memory,
                          const float* __restrict__ clutter,
                          float* __restrict__ out) {
    extern __shared__ float smem[];
    float* Ws  = smem;                     // [k=128][n=128] (+pad), tf32 after cvt
    float* As0 = smem + TILE_FLOATS;       // [m=128][kpos=128] (+pad)
    float* As1 = As0 + TILE_FLOATS;

    const int tid  = threadIdx.x;
    const int wid  = tid >> 5;
    const int lane = tid & 31;
    const int g    = lane >> 2;            // 0..7
    const int tg   = lane & 3;             // 0..3
    const int wm   = (wid >> 2) * 64;      // 0 / 64
    const int wn   = (wid & 3) * 32;       // 0..96
    const int n0   = blockIdx.x * 128;

    // W source: raw fp32 rows (k-major), 128 contiguous floats per row
    const float* wsrc;
    size_t ldw;
    if (n0 < CJ) {
        wsrc = memory + (size_t)(n0 >> 9) * (MESH_DIM * MAX_N) + (n0 & 511);
        ldw  = MAX_N;
    } else {
        wsrc = clutter + (n0 - CJ);
        ldw  = NCLUT_TOT;
    }

    // ---- initial loads: raw W tile + A tile 0 (cp.async) ----
    {
        const uint32_t wbase = smem_u32(Ws);
        const uint32_t abase = smem_u32(As0);
        for (int c = tid; c < 4096; c += 256) {
            const int row = c >> 5, cid = c & 31;
            CP_ASYNC16(wbase + (uint32_t)(row * LDK + cid * 4) * 4,
                       wsrc + (size_t)row * ldw + cid * 4);
            CP_ASYNC16(abase + (uint32_t)(row * LDK + cid * 4) * 4,
                       g_A + (size_t)row * MESH_DIM + cid * 4);
        }
        CP_COMMIT();
        CP_WAIT0();
    }
    __syncthreads();

    // ---- in-smem tf32 conversion of W (once per CTA) ----
    for (int e = tid; e < 4096; e += 256) {
        const int k = e >> 5, nc = (e & 31) * 4;
        float4 v = *reinterpret_cast<float4*>(Ws + k * LDK + nc);
        v.x = to_tf32(v.x); v.y = to_tf32(v.y);
        v.z = to_tf32(v.z); v.w = to_tf32(v.w);
        *reinterpret_cast<float4*>(Ws + k * LDK + nc) = v;
    }
    __syncthreads();

    float* bufs[2] = { As0, As1 };
    const int nidx = wn + g;               // base n for B frags (+ ni*8)

    for (int mt = 0; mt < 16; mt++) {
        const float* cur = bufs[mt & 1];

        if (mt < 15) {
            const float* asrc = g_A + ((size_t)(mt + 1) * 128) * MESH_DIM;
            const uint32_t abase = smem_u32(bufs[(mt + 1) & 1]);
            for (int c = tid; c < 4096; c += 256) {
                const int row = c >> 5, cid = c & 31;
                CP_ASYNC16(abase + (uint32_t)(row * LDK + cid * 4) * 4,
                           asrc + (size_t)row * MESH_DIM + cid * 4);
            }
            CP_COMMIT();
        }

        float acc[4][4][4];
#pragma unroll
        for (int mi = 0; mi < 4; mi++)
#pragma unroll
            for (int ni = 0; ni < 4; ni++)
#pragma unroll
                for (int r = 0; r < 4; r++) acc[mi][ni][r] = 0.0f;

#pragma unroll
        for (int ks = 0; ks < 16; ks++) {
            const int colb = ks * 8 + 2 * tg;     // A: permuted pos (k=tg, k=tg+4)
            const int colk = ks * 8 + tg;         // B: logical k row

            uint32_t a0[4], a1[4], a2[4], a3[4];
#pragma unroll
            for (int mi = 0; mi < 4; mi++) {
                const float* p = &cur[(wm + mi * 16 + g) * LDK + colb];
                const float2 lo = *reinterpret_cast<const float2*>(p);
                const float2 hi = *reinterpret_cast<const float2*>(p + 8 * LDK);
                a0[mi] = __float_as_uint(lo.x);
                a2[mi] = __float_as_uint(lo.y);
                a1[mi] = __float_as_uint(hi.x);
                a3[mi] = __float_as_uint(hi.y);
            }
            uint32_t b0[4], b1[4];
#pragma unroll
            for (int ni = 0; ni < 4; ni++) {
                b0[ni] = __float_as_uint(Ws[colk * LDK + nidx + ni * 8]);
                b1[ni] = __float_as_uint(Ws[(colk + 4) * LDK + nidx + ni * 8]);
            }
#pragma unroll
            for (int mi = 0; mi < 4; mi++)
#pragma unroll
                for (int ni = 0; ni < 4; ni++)
                    mma_tf32(acc[mi][ni][0], acc[mi][ni][1],
                             acc[mi][ni][2], acc[mi][ni][3],
                             a0[mi], a1[mi], a2[mi], a3[mi],
                             b0[ni], b1[ni]);
        }

        // ---- store D tile ----
#pragma unroll
        for (int mi = 0; mi < 4; mi++) {
            const size_t m = (size_t)(mt * 128 + wm + mi * 16 + g);
#pragma unroll
            for (int ni = 0; ni < 4; ni++) {
                float* o = out + m * NTOT + (n0 + wn + ni * 8 + 2 * tg);
                float2 v0; v0.x = acc[mi][ni][0]; v0.y = acc[mi][ni][1];
                float2 v1; v1.x = acc[mi][ni][2]; v1.y = acc[mi][ni][3];
                *reinterpret_cast<float2*>(o)            = v0;
                *reinterpret_cast<float2*>(o + 8 * NTOT) = v1;
            }
        }

        if (mt < 15) {
            CP_WAIT0();
            __syncthreads();
        }
    }
}

// ---------------------------------------------------------------------------
// Launcher — exactly 2 kernels (ncu -s 5 -c 1 lands on the GEMM).
// ---------------------------------------------------------------------------
#define GEMM_DSMEM (3 * TILE_FLOATS * 4)   // 208,896 bytes

extern "C" void kernel_launch(void* const* d_in, const int* in_sizes, int n_in,
                              void* d_out, int out_size) {
    const float* features = (const float*)d_in[0];
    const int*   visible  = (const int*)d_in[1];
    const int*   label    = (const int*)d_in[2];
    const float* memory   = (const float*)d_in[3];
    const float* clutter  = (const float*)d_in[4];
    const int*   lru      = (const int*)d_in[5];

    float* out = (float*)d_out;
    float* out_sim  = out + OUT_SIM_OFF;
    float* out_nsim = out + OUT_NSIM_OFF;
    float* out_mem  = out + OUT_MEM_OFF;
    float* out_cb   = out + OUT_CB_OFF;

    cudaFuncSetAttribute(sim_gemm_tf32_kernel,
                         cudaFuncAttributeMaxDynamicSharedMemorySize, GEMM_DSMEM);

    prep_fused_kernel<<<64 + 128 + 256 + NCLUT_TOT / 256, 256>>>(
        features, visible, label, memory, clutter, lru,
        out_nsim, out_mem, out_cb);
    sim_gemm_tf32_kernel<<<NTOT / 128, 256, GEMM_DSMEM>>>(memory, clutter, out_sim);
}

// round 7
// speedup vs baseline: 2.8880x; 1.0291x over previous
#include <cuda_runtime.h>
#include <cuda_bf16.h>
#include <cstdint>

// Problem constants
#define MAX_N     512
#define N_CLASSES 64
#define MESH_DIM  128
#define NUM_CLUT  5
#define BANK_SIZE 4096
#define BATCH     4
#define FEAT_ROWS (MAX_N + NUM_CLUT)          // 517
#define CJ        (N_CLASSES * MAX_N)          // 32768
#define NCLUT_TOT (NUM_CLUT * BANK_SIZE)       // 20480
#define NTOT      (CJ + NCLUT_TOT)             // 53248
#define M_TOT     (BATCH * MAX_N)              // 2048

// Output offsets (element counts)
#define OUT_SIM_OFF   0ULL
#define OUT_SIM_SZ    ((unsigned long long)BATCH * MAX_N * NTOT)
#define OUT_NSIM_OFF  (OUT_SIM_OFF + OUT_SIM_SZ)
#define OUT_NSIM_SZ   ((unsigned long long)BATCH * NUM_CLUT * CJ)
#define OUT_MEM_OFF   (OUT_NSIM_OFF + OUT_NSIM_SZ)
#define OUT_MEM_SZ    ((unsigned long long)N_CLASSES * MESH_DIM * MAX_N)
#define OUT_CB_OFF    (OUT_MEM_OFF + OUT_MEM_SZ)

// ---------------------------------------------------------------------------
// tf32 A scratch (device global — allocation-free rule).
// Row-major [m][k], k permuted within 8-blocks: pos 2t,2t+1 hold k=t,t+4
// so A fragment pairs (k, k+4) are one LDS.64.
// ---------------------------------------------------------------------------
__device__ __align__(16) float g_A[(size_t)M_TOT * MESH_DIM];   // 1 MB

__device__ __forceinline__ int kpos(int k) {
    return (k & ~7) | (((k & 3) << 1) | ((k >> 2) & 1));
}

__device__ __forceinline__ float to_tf32(float x) {
    uint32_t u;
    asm("cvt.rna.tf32.f32 %0, %1;" : "=r"(u) : "f"(x));
    return __uint_as_float(u);
}

__device__ __forceinline__ uint32_t smem_u32(const void* p) {
    uint32_t a;
    asm("{ .reg .u64 t; cvta.to.shared.u64 t, %1; cvt.u32.u64 %0, t; }" : "=r"(a) : "l"(p));
    return a;
}

#define CP_ASYNC16(saddr, gptr) \
    asm volatile("cp.async.cg.shared.global [%0], [%1], 16;" :: "r"(saddr), "l"(gptr))
#define CP_COMMIT() asm volatile("cp.async.commit_group;")
#define CP_WAIT0()  asm volatile("cp.async.wait_group 0;")

// m16n8k8 tf32 MMA (sm_80 baseline — works at compute_103)
__device__ __forceinline__ void mma_tf32(float& c0, float& c1, float& c2, float& c3,
                                         uint32_t a0, uint32_t a1, uint32_t a2, uint32_t a3,
                                         uint32_t b0, uint32_t b1) {
    asm volatile(
        "mma.sync.aligned.m16n8k8.row.col.f32.tf32.tf32.f32 "
        "{%0,%1,%2,%3}, {%4,%5,%6,%7}, {%8,%9}, {%0,%1,%2,%3};"
        : "+f"(c0), "+f"(c1), "+f"(c2), "+f"(c3)
        : "r"(a0), "r"(a1), "r"(a2), "r"(a3), "r"(b0), "r"(b1));
}

// ---------------------------------------------------------------------------
// Launch #1 — fused prep: A tf32 convert + noise_sim + mem_update + clutter.
//   blocks [0,64)     : A convert
//   blocks [64,192)   : noise similarity
//   blocks [192,448)  : memory update
//   blocks [448,528)  : clutter bank
// ---------------------------------------------------------------------------
__global__ __launch_bounds__(256)
void prep_fused_kernel(const float* __restrict__ features,
                       const int* __restrict__ visible,
                       const int* __restrict__ label,
                       const float* __restrict__ memory,
                       const float* __restrict__ clutter,
                       const int* __restrict__ lru,
                       float* __restrict__ out_nsim,
                       float* __restrict__ out_mem,
                       float* __restrict__ out_cb) {
    const int bx = blockIdx.x;

    if (bx < 64) {
        // ================= A conversion =================
        const int base = bx * 4096;
        for (int e = threadIdx.x; e < 4096; e += 256) {
            const int idx = base + e;
            const int m = idx >> 7;
            const int k = idx & 127;
            const int b = m >> 9;
            const int i = m & 511;
            const float x = features[(size_t)(b * FEAT_ROWS + i) * MESH_DIM + k];
            g_A[((size_t)m << 7) | kpos(k)] = to_tf32(x);
        }
        return;
    }

    if (bx < 192) {
        // ================= noise similarity =================
        __shared__ float ns[BATCH * NUM_CLUT][MESH_DIM];
        const int blk = bx - 64;
        const int c = blk >> 1;
        const int j = (blk & 1) * 256 + threadIdx.x;

        for (int idx = threadIdx.x; idx < BATCH * NUM_CLUT * MESH_DIM; idx += 256) {
            const int r = idx >> 7;
            const int v = idx & 127;
            const int bb = r / NUM_CLUT;
            const int kk = r % NUM_CLUT;
            ns[r][v] = features[(size_t)(bb * FEAT_ROWS + MAX_N + kk) * MESH_DIM + v];
        }
        __syncthreads();

        float acc[BATCH * NUM_CLUT];
#pragma unroll
        for (int r = 0; r < BATCH * NUM_CLUT; r++) acc[r] = 0.0f;

        const float* mp = memory + (size_t)c * (MESH_DIM * MAX_N) + j;
#pragma unroll 4
        for (int v = 0; v < MESH_DIM; v++) {
            const float mv = mp[(size_t)v * MAX_N];
#pragma unroll
            for (int r = 0; r < BATCH * NUM_CLUT; r++) acc[r] += ns[r][v] * mv;
        }
#pragma unroll
        for (int r = 0; r < BATCH * NUM_CLUT; r++)
            out_nsim[(size_t)r * CJ + c * MAX_N + j] = acc[r];
        return;
    }

    if (bx < 448) {
        // ================= memory update (float4 over j) =================
        __shared__ float4 ssqs[8][32];
        const int blk = bx - 192;
        const int c   = blk >> 2;
        const int j0  = (blk & 3) * 128;
        const int t   = threadIdx.x;
        const int jx  = t & 31;
        const int vy  = t >> 5;               // 0..7
        const int j   = j0 + jx * 4;

        int lbl[BATCH];
#pragma unroll
        for (int bb = 0; bb < BATCH; bb++) lbl[bb] = label[bb];
        int cnt = 0;
#pragma unroll
        for (int bb = 0; bb < BATCH; bb++) cnt += (lbl[bb] == c) ? 1 : 0;
        const float inv = (cnt > 0) ? (1.0f / (float)cnt) : 0.0f;

        float w[BATCH][4];
#pragma unroll
        for (int bb = 0; bb < BATCH; bb++)
#pragma unroll
            for (int d = 0; d < 4; d++)
                w[bb][d] = (lbl[bb] == c && visible[bb * MAX_N + j + d] != 0) ? inv : 0.0f;

        const float* mrow = memory + (size_t)c * (MESH_DIM * MAX_N) + j;
        float4 vals[16];
        float4 ssq = make_float4(0.f, 0.f, 0.f, 0.f);
#pragma unroll
        for (int vv = 0; vv < 16; vv++) {
            const int v = vy * 16 + vv;
            float4 m = *reinterpret_cast<const float4*>(mrow + (size_t)v * MAX_N);
            if (cnt > 0) {
                float s[4];
#pragma unroll
                for (int d = 0; d < 4; d++) {
                    s[d] = 0.0f;
#pragma unroll
                    for (int bb = 0; bb < BATCH; bb++)
                        s[d] += w[bb][d] *
                                features[(size_t)(bb * FEAT_ROWS + j + d) * MESH_DIM + v];
                }
                m.x = 0.9f * m.x + 0.1f * s[0];
                m.y = 0.9f * m.y + 0.1f * s[1];
                m.z = 0.9f * m.z + 0.1f * s[2];
                m.w = 0.9f * m.w + 0.1f * s[3];
            }
            vals[vv] = m;
            ssq.x += m.x * m.x;  ssq.y += m.y * m.y;
            ssq.z += m.z * m.z;  ssq.w += m.w * m.w;
        }
        ssqs[vy][jx] = ssq;
        __syncthreads();

        float4 tot = make_float4(0.f, 0.f, 0.f, 0.f);
#pragma unroll
        for (int y = 0; y < 8; y++) {
            const float4 q = ssqs[y][jx];
            tot.x += q.x; tot.y += q.y; tot.z += q.z; tot.w += q.w;
        }
        float4 rn;
        rn.x = 1.0f / fmaxf(sqrtf(tot.x), 1e-12f);
        rn.y = 1.0f / fmaxf(sqrtf(tot.y), 1e-12f);
        rn.z = 1.0f / fmaxf(sqrtf(tot.z), 1e-12f);
        rn.w = 1.0f / fmaxf(sqrtf(tot.w), 1e-12f);

        float* orow = out_mem + (size_t)c * (MESH_DIM * MAX_N) + j;
#pragma unroll
        for (int vv = 0; vv < 16; vv++) {
            const int v = vy * 16 + vv;
            float4 m = vals[vv];
            m.x *= rn.x; m.y *= rn.y; m.z *= rn.z; m.w *= rn.w;
            *reinterpret_cast<float4*>(orow + (size_t)v * MAX_N) = m;
        }
        return;
    }

    // ================= clutter bank update =================
    {
        const int n = (bx - 448) * 256 + threadIdx.x;   // 0..20479
        const int new_lru = (lru[0] + 1) % (BANK_SIZE / BATCH);
        const int start = new_lru * (NUM_CLUT * BATCH);

        const bool upd = (n >= start) && (n < start + NUM_CLUT * BATCH);
        const int mm = n - start;
        const int bb = upd ? (mm / NUM_CLUT) : 0;
        const int kk = upd ? (mm % NUM_CLUT) : 0;
        const float* nsrc = features + (size_t)(bb * FEAT_ROWS + MAX_N + kk) * MESH_DIM;

        float ssq = 0.0f;
#pragma unroll 8
        for (int v = 0; v < MESH_DIM; v++) {
            const float val = upd ? nsrc[v] : clutter[(size_t)v * NCLUT_TOT + n];
            ssq += val * val;
        }
        const float rn = 1.0f / fmaxf(sqrtf(ssq), 1e-12f);

#pragma unroll 8
        for (int v = 0; v < MESH_DIM; v++) {
            const float val = upd ? nsrc[v] : clutter[(size_t)v * NCLUT_TOT + n];
            out_cb[(size_t)v * NCLUT_TOT + n] = val * rn;
        }
    }
}

// ---------------------------------------------------------------------------
// Launch #2 — tf32 mma.sync GEMM, 512 threads / 16 warps.
//   out[m][n] = A[m][:128] . W[:][n]
// W slice loaded RAW (coalesced rows) into smem [k][n] (ld 136), tf32-converted
// in-smem once per CTA. A 128x128 m-tiles (pre-converted, k-permuted) double-
// buffered via cp.async. 16 warps = 4m x 4n, warp tile 32m x 32n.
// ---------------------------------------------------------------------------
#define LDK 136
#define TILE_FLOATS (128 * LDK)

__global__ __launch_bounds__(512)
void sim_gemm_tf32_kernel(const float* __restrict__ memory,
                          const float* __restrict__ clutter,
                          float* __restrict__ out) {
    extern __shared__ float smem[];
    float* Ws  = smem;                     // [k=128][n=128] (+pad), tf32 after cvt
    float* As0 = smem + TILE_FLOATS;       // [m=128][kpos=128] (+pad)
    float* As1 = As0 + TILE_FLOATS;

    const int tid  = threadIdx.x;
    const int wid  = tid >> 5;
    const int lane = tid & 31;
    const int g    = lane >> 2;            // 0..7
    const int tg   = lane & 3;             // 0..3
    const int wm   = (wid >> 2) * 32;      // 0,32,64,96
    const int wn   = (wid & 3) * 32;       // 0,32,64,96
    const int n0   = blockIdx.x * 128;

    // W source: raw fp32 rows (k-major), 128 contiguous floats per row
    const float* wsrc;
    size_t ldw;
    if (n0 < CJ) {
        wsrc = memory + (size_t)(n0 >> 9) * (MESH_DIM * MAX_N) + (n0 & 511);
        ldw  = MAX_N;
    } else {
        wsrc = clutter + (n0 - CJ);
        ldw  = NCLUT_TOT;
    }

    // ---- initial loads: raw W tile + A tile 0 (cp.async) ----
    {
        const uint32_t wbase = smem_u32(Ws);
        const uint32_t abase = smem_u32(As0);
        for (int c = tid; c < 4096; c += 512) {
            const int row = c >> 5, cid = c & 31;
            CP_ASYNC16(wbase + (uint32_t)(row * LDK + cid * 4) * 4,
                       wsrc + (size_t)row * ldw + cid * 4);
            CP_ASYNC16(abase + (uint32_t)(row * LDK + cid * 4) * 4,
                       g_A + (size_t)row * MESH_DIM + cid * 4);
        }
        CP_COMMIT();
        CP_WAIT0();
    }
    __syncthreads();

    // ---- in-smem tf32 conversion of W (once per CTA) ----
    for (int e = tid; e < 4096; e += 512) {
        const int k = e >> 5, nc = (e & 31) * 4;
        float4 v = *reinterpret_cast<float4*>(Ws + k * LDK + nc);
        v.x = to_tf32(v.x); v.y = to_tf32(v.y);
        v.z = to_tf32(v.z); v.w = to_tf32(v.w);
        *reinterpret_cast<float4*>(Ws + k * LDK + nc) = v;
    }
    __syncthreads();

    float* bufs[2] = { As0, As1 };
    const int nidx = wn + g;               // base n for B frags (+ ni*8)

    for (int mt = 0; mt < 16; mt++) {
        const float* cur = bufs[mt & 1];

        if (mt < 15) {
            const float* asrc = g_A + ((size_t)(mt + 1) * 128) * MESH_DIM;
            const uint32_t abase = smem_u32(bufs[(mt + 1) & 1]);
            for (int c = tid; c < 4096; c += 512) {
                const int row = c >> 5, cid = c & 31;
                CP_ASYNC16(abase + (uint32_t)(row * LDK + cid * 4) * 4,
                           asrc + (size_t)row * MESH_DIM + cid * 4);
            }
            CP_COMMIT();
        }

        float acc[2][4][4];
#pragma unroll
        for (int mi = 0; mi < 2; mi++)
#pragma unroll
            for (int ni = 0; ni < 4; ni++)
#pragma unroll
                for (int r = 0; r < 4; r++) acc[mi][ni][r] = 0.0f;

#pragma unroll
        for (int ks = 0; ks < 16; ks++) {
            const int colb = ks * 8 + 2 * tg;     // A: permuted pos (k=tg, k=tg+4)
            const int colk = ks * 8 + tg;         // B: logical k row

            uint32_t a0[2], a1[2], a2[2], a3[2];
#pragma unroll
            for (int mi = 0; mi < 2; mi++) {
                const float* p = &cur[(wm + mi * 16 + g) * LDK + colb];
                const float2 lo = *reinterpret_cast<const float2*>(p);
                const float2 hi = *reinterpret_cast<const float2*>(p + 8 * LDK);
                a0[mi] = __float_as_uint(lo.x);
                a2[mi] = __float_as_uint(lo.y);
                a1[mi] = __float_as_uint(hi.x);
                a3[mi] = __float_as_uint(hi.y);
            }
            uint32_t b0[4], b1[4];
#pragma unroll
            for (int ni = 0; ni < 4; ni++) {
                b0[ni] = __float_as_uint(Ws[colk * LDK + nidx + ni * 8]);
                b1[ni] = __float_as_uint(Ws[(colk + 4) * LDK + nidx + ni * 8]);
            }
#pragma unroll
            for (int mi = 0; mi < 2; mi++)
#pragma unroll
                for (int ni = 0; ni < 4; ni++)
                    mma_tf32(acc[mi][ni][0], acc[mi][ni][1],
                             acc[mi][ni][2], acc[mi][ni][3],
                             a0[mi], a1[mi], a2[mi], a3[mi],
                             b0[ni], b1[ni]);
        }

        // ---- store D tile ----
#pragma unroll
        for (int mi = 0; mi < 2; mi++) {
            const size_t m = (size_t)(mt * 128 + wm + mi * 16 + g);
#pragma unroll
            for (int ni = 0; ni < 4; ni++) {
                float* o = out + m * NTOT + (n0 + wn + ni * 8 + 2 * tg);
                float2 v0; v0.x = acc[mi][ni][0]; v0.y = acc[mi][ni][1];
                float2 v1; v1.x = acc[mi][ni][2]; v1.y = acc[mi][ni][3];
                *reinterpret_cast<float2*>(o)            = v0;
                *reinterpret_cast<float2*>(o + 8 * NTOT) = v1;
            }
        }

        if (mt < 15) {
            CP_WAIT0();
            __syncthreads();
        }
    }
}

// ---------------------------------------------------------------------------
// Launcher — exactly 2 kernels (ncu -s 5 -c 1 lands on the GEMM).
// ---------------------------------------------------------------------------
#define GEMM_DSMEM (3 * TILE_FLOATS * 4)   // 208,896 bytes

extern "C" void kernel_launch(void* const* d_in, const int* in_sizes, int n_in,
                              void* d_out, int out_size) {
    const float* features = (const float*)d_in[0];
    const int*   visible  = (const int*)d_in[1];
    const int*   label    = (const int*)d_in[2];
    const float* memory   = (const float*)d_in[3];
    const float* clutter  = (const float*)d_in[4];
    const int*   lru      = (const int*)d_in[5];

    float* out = (float*)d_out;
    float* out_sim  = out + OUT_SIM_OFF;
    float* out_nsim = out + OUT_NSIM_OFF;
    float* out_mem  = out + OUT_MEM_OFF;
    float* out_cb   = out + OUT_CB_OFF;

    cudaFuncSetAttribute(sim_gemm_tf32_kernel,
                         cudaFuncAttributeMaxDynamicSharedMemorySize, GEMM_DSMEM);

    prep_fused_kernel<<<64 + 128 + 256 + NCLUT_TOT / 256, 256>>>(
        features, visible, label, memory, clutter, lru,
        out_nsim, out_mem, out_cb);
    sim_gemm_tf32_kernel<<<NTOT / 128, 512, GEMM_DSMEM>>>(memory, clutter, out_sim);
}